// round 14
// baseline (speedup 1.0000x reference)
#include <cuda_runtime.h>
#include <cuda_fp16.h>
#include <cstdint>

// Problem shape: n=4096, m=32768, d=128
#define N_FIX 4096
#define M_FIX 32768
#define D_FIX 128
#define TOT_TILES 8192          // (4096/128) * (32768/128)
#define CTAS 304
#define TPC 27                  // ceil(8192/304)
#define MARGIN 0.5f
#define INV_N (1.0f / 4096.0f)

#define ROWB 272                // padded smem row stride (bytes): 256B data + 16B pad
#define TILE_SM (128 * ROWB)    // 34816 B

// smem layout (bytes)
#define SM_A     0
#define SM_B0    34816
#define SM_B1    69632
#define SM_LABA  104448
#define SM_LABB0 104960
#define SM_LABB1 105472
#define SM_WSUM  105984         // 16 floats
#define SM_TOTAL 106048

// fp16 scratch (allocation-free rule: __device__ globals)
__device__ __half g_A[N_FIX * D_FIX];
__device__ __half g_B[M_FIX * D_FIX];
__device__ int g_labA[N_FIX];
__device__ int g_labB[M_FIX];

// ---------------------------------------------------------------------------
// Prep: fp32 -> fp16, label extraction (level 0), out zeroing.
// DRAM-bound (~28MB); wide grid for MLP.
// ---------------------------------------------------------------------------
__global__ void prep_kernel(const float4* __restrict__ emb,
                            const long long* __restrict__ labels,
                            const float4* __restrict__ ref,
                            const long long* __restrict__ ref_labels,
                            float* __restrict__ out) {
    int tid = blockIdx.x * blockDim.x + threadIdx.x;
    int stride = gridDim.x * blockDim.x;
    if (tid == 0) out[0] = 0.0f;
    for (int i = tid; i < N_FIX * D_FIX / 4; i += stride) {
        float4 v = emb[i];
        __half2* dst = (__half2*)&g_A[i * 4];
        dst[0] = __floats2half2_rn(v.x, v.y);
        dst[1] = __floats2half2_rn(v.z, v.w);
    }
    for (int i = tid; i < M_FIX * D_FIX / 4; i += stride) {
        float4 v = ref[i];
        __half2* dst = (__half2*)&g_B[i * 4];
        dst[0] = __floats2half2_rn(v.x, v.y);
        dst[1] = __floats2half2_rn(v.z, v.w);
    }
    for (int i = tid; i < N_FIX; i += stride)
        g_labA[i] = (int)labels[(long long)i * 2];
    for (int i = tid; i < M_FIX; i += stride)
        g_labB[i] = (int)ref_labels[(long long)i * 2];
}

// ---------------------------------------------------------------------------
// PTX helpers
// ---------------------------------------------------------------------------
__device__ __forceinline__ uint32_t smem_u32(const void* p) {
    return (uint32_t)__cvta_generic_to_shared(p);
}
__device__ __forceinline__ void cp16(uint32_t saddr, const void* gaddr) {
    asm volatile("cp.async.cg.shared.global [%0], [%1], 16;" :: "r"(saddr), "l"(gaddr));
}
__device__ __forceinline__ void cp_commit() { asm volatile("cp.async.commit_group;"); }
__device__ __forceinline__ void cp_wait0()  { asm volatile("cp.async.wait_group 0;" ::: "memory"); }

__device__ __forceinline__ void ldsm_x4(uint32_t* r, uint32_t addr) {
    asm volatile("ldmatrix.sync.aligned.m8n8.x4.shared.b16 {%0,%1,%2,%3}, [%4];"
                 : "=r"(r[0]), "=r"(r[1]), "=r"(r[2]), "=r"(r[3]) : "r"(addr));
}

// f16 inputs, f16 accumulators: C fragment = 2 x f16x2 regs
__device__ __forceinline__ void mma_f16(uint32_t* c, const uint32_t* a, uint32_t b0, uint32_t b1) {
    asm volatile(
        "mma.sync.aligned.m16n8k16.row.col.f16.f16.f16.f16 "
        "{%0,%1}, {%2,%3,%4,%5}, {%6,%7}, {%0,%1};"
        : "+r"(c[0]), "+r"(c[1])
        : "r"(a[0]), "r"(a[1]), "r"(a[2]), "r"(a[3]), "r"(b0), "r"(b1));
}

// load a 128x128 fp16 tile (rows of 256B) into padded smem: 2048 x 16B chunks
__device__ __forceinline__ void load_tile(uint32_t sbase, const __half* g, int tid) {
#pragma unroll
    for (int j = 0; j < 4; j++) {
        int idx = tid + j * 512;          // 0..2047
        int r = idx >> 4, c = idx & 15;
        cp16(sbase + r * ROWB + c * 16, g + r * D_FIX + c * 8);
    }
}

// ---------------------------------------------------------------------------
// Persistent fp16 HMMA kernel: 128x128x128 tiles, A resident, B double-buffered
// 512 threads = 16 warps, warp tile 32x32 (4x4 warp grid), f16 accumulators
// ---------------------------------------------------------------------------
__global__ __launch_bounds__(512, 2)
void xbm_h_kernel(float* __restrict__ out) {
    extern __shared__ char smem[];
    const int tid = threadIdx.x, warp = tid >> 5, lane = tid & 31;
    const uint32_t sbase = smem_u32(smem);
    const int* labA_s = (const int*)(smem + SM_LABA);
    float* wsum = (float*)(smem + SM_WSUM);

    int t0 = blockIdx.x * TPC;
    int t1 = t0 + TPC;
    if (t1 > TOT_TILES) t1 = TOT_TILES;
    if (t0 >= t1) { return; }

    const int wm = (warp & 3) * 32;       // row offset of warp tile
    const int wn = (warp >> 2) * 32;      // col offset of warp tile

    // ldmatrix lane-invariant base addresses (k-step advances +32 bytes)
    const uint32_t aBase = sbase + SM_A + (uint32_t)(wm + (lane & 15)) * ROWB
                         + ((lane >> 4) << 4);
    const uint32_t bLane = (uint32_t)(wn + (lane & 7) + ((lane >> 4) << 3)) * ROWB
                         + (((lane >> 3) & 1) << 4);

    // epilogue label indices for this thread
    const int rowA0 = wm + (lane >> 2);
    const int colB0 = wn + ((lane & 3) << 1);

    // prologue: A(nb0) + labA + B(t0) + labB(t0)
    int cur_nb = t0 >> 8;
    {
        int mb = t0 & 255, buf = t0 & 1;
        load_tile(sbase + SM_A, g_A + (size_t)cur_nb * 128 * D_FIX, tid);
        load_tile(sbase + SM_B0 + buf * TILE_SM, g_B + (size_t)mb * 128 * D_FIX, tid);
        if (tid < 32) {
            cp16(sbase + SM_LABA + tid * 16, g_labA + cur_nb * 128 + tid * 4);
            cp16(sbase + SM_LABB0 + buf * 512 + tid * 16, g_labB + mb * 128 + tid * 4);
        }
        cp_commit();
    }

    float ts[4] = {0.0f, 0.0f, 0.0f, 0.0f};   // 4 independent chains

    for (int t = t0; t < t1; ++t) {
        cp_wait0();
        __syncthreads();                      // B(t) (+A) visible to all

        if ((t >> 8) != cur_nb) {             // A is stale for this tile: reload now
            cur_nb = t >> 8;
            load_tile(sbase + SM_A, g_A + (size_t)cur_nb * 128 * D_FIX, tid);
            if (tid < 32) cp16(sbase + SM_LABA + tid * 16, g_labA + cur_nb * 128 + tid * 4);
            cp_commit();
            cp_wait0();
            __syncthreads();
        }

        const int buf = t & 1;
        const uint32_t bBase = sbase + (buf ? SM_B1 : SM_B0) + bLane;
        const int* labB_s = (const int*)(smem + (buf ? SM_LABB1 : SM_LABB0));

        // prefetch next B while computing (overwrites buf^1 = tile t-1's buffer)
        if (t + 1 < t1) {
            int nmb = (t + 1) & 255, nbuf = (t + 1) & 1;
            load_tile(sbase + SM_B0 + nbuf * TILE_SM, g_B + (size_t)nmb * 128 * D_FIX, tid);
            if (tid < 32) cp16(sbase + SM_LABB0 + nbuf * 512 + tid * 16,
                               g_labB + nmb * 128 + tid * 4);
            cp_commit();
        }

        // ---- compute 32x32 warp tile, K=128 (8 k-steps of 16), f16 acc ----
        uint32_t acc[2][4][2];
#pragma unroll
        for (int mi = 0; mi < 2; mi++)
#pragma unroll
            for (int ni = 0; ni < 4; ni++) {
                acc[mi][ni][0] = 0u; acc[mi][ni][1] = 0u;
            }

#pragma unroll
        for (int ks = 0; ks < 8; ks++) {
            const int k0 = ks * 32;            // byte offset
            uint32_t a[2][4], b[2][4];
#pragma unroll
            for (int mi = 0; mi < 2; mi++)
                ldsm_x4(a[mi], aBase + mi * (16 * ROWB) + k0);
#pragma unroll
            for (int p = 0; p < 2; p++)
                ldsm_x4(b[p], bBase + p * (16 * ROWB) + k0);
#pragma unroll
            for (int mi = 0; mi < 2; mi++)
#pragma unroll
                for (int ni = 0; ni < 4; ni++)
                    mma_f16(acc[mi][ni], a[mi],
                            b[ni >> 1][(ni & 1) * 2], b[ni >> 1][(ni & 1) * 2 + 1]);
        }

        // ---- epilogue: unpack f16x2, branchless, 4 independent chains ----
#pragma unroll
        for (int mi = 0; mi < 2; mi++) {
            const int la0 = labA_s[rowA0 + mi * 16];
            const int la1 = labA_s[rowA0 + mi * 16 + 8];
#pragma unroll
            for (int ni = 0; ni < 4; ni++) {
                const int lb0 = labB_s[colB0 + ni * 8];
                const int lb1 = labB_s[colB0 + ni * 8 + 1];
                const float2 lo = __half22float2(*(const __half2*)&acc[mi][ni][0]);
                const float2 hi = __half22float2(*(const __half2*)&acc[mi][ni][1]);
                const float sv[4] = {lo.x, lo.y, hi.x, hi.y};
#pragma unroll
                for (int k = 0; k < 4; k++) {
                    const float s = sv[k];
                    const int lA = (k >> 1) ? la1 : la0;
                    const int lB = (k & 1) ? lb1 : lb0;
                    float v;
                    if (lA == lB) v = fmaxf(1.0f - s, 0.0f);
                    else          v = (s > MARGIN) ? s : 0.0f;
                    ts[k] += v;
                }
            }
        }
    }

    // block reduce + single atomic
    float tsum = (ts[0] + ts[1]) + (ts[2] + ts[3]);
#pragma unroll
    for (int off = 16; off > 0; off >>= 1)
        tsum += __shfl_down_sync(0xFFFFFFFFu, tsum, off);
    if (lane == 0) wsum[warp] = tsum;
    __syncthreads();
    if (tid == 0) {
        float s = 0.0f;
#pragma unroll
        for (int i = 0; i < 16; i++) s += wsum[i];
        atomicAdd(out, s * INV_N);
    }
}

// ---------------------------------------------------------------------------
extern "C" void kernel_launch(void* const* d_in, const int* in_sizes, int n_in,
                              void* d_out, int out_size) {
    const float*     emb        = (const float*)d_in[0];
    const long long* labels     = (const long long*)d_in[1];
    const float*     ref        = (const float*)d_in[2];
    const long long* ref_labels = (const long long*)d_in[3];
    float* out = (float*)d_out;

    cudaFuncSetAttribute(xbm_h_kernel,
                         cudaFuncAttributeMaxDynamicSharedMemorySize, SM_TOTAL);

    prep_kernel<<<1184, 256>>>((const float4*)emb, labels, (const float4*)ref,
                               ref_labels, out);
    xbm_h_kernel<<<CTAS, 512, SM_TOTAL>>>(out);
}

// round 16
// speedup vs baseline: 1.0760x; 1.0760x over previous
#include <cuda_runtime.h>
#include <cuda_fp16.h>
#include <cstdint>

// Problem shape: n=4096, m=32768, d=128
#define N_FIX 4096
#define M_FIX 32768
#define D_FIX 128
#define TOT_TILES 8192          // (4096/128) * (32768/128)
#define CTAS 304
#define TPC 27                  // ceil(8192/304)
#define MARGIN 0.5f
#define INV_N (1.0f / 4096.0f)

#define ROWB 272                // padded smem row stride (bytes): 256B data + 16B pad
#define TILE_SM (128 * ROWB)    // 34816 B

// smem layout (bytes)
#define SM_A     0
#define SM_B0    34816
#define SM_B1    69632
#define SM_LABA  104448
#define SM_LABB0 104960
#define SM_LABB1 105472
#define SM_WSUM  105984         // 16 floats
#define SM_TOTAL 106048

// fp16 scratch (allocation-free rule: __device__ globals)
__device__ __half g_A[N_FIX * D_FIX];
__device__ __half g_B[M_FIX * D_FIX];
__device__ int g_labA[N_FIX];
__device__ int g_labB[M_FIX];

// ---------------------------------------------------------------------------
// Prep: fp32 -> fp16, label extraction (level 0), out zeroing
// ---------------------------------------------------------------------------
__global__ void prep_kernel(const float4* __restrict__ emb,
                            const long long* __restrict__ labels,
                            const float4* __restrict__ ref,
                            const long long* __restrict__ ref_labels,
                            float* __restrict__ out) {
    int tid = blockIdx.x * blockDim.x + threadIdx.x;
    int stride = gridDim.x * blockDim.x;
    if (tid == 0) out[0] = 0.0f;
    for (int i = tid; i < N_FIX * D_FIX / 4; i += stride) {
        float4 v = emb[i];
        __half2* dst = (__half2*)&g_A[i * 4];
        dst[0] = __floats2half2_rn(v.x, v.y);
        dst[1] = __floats2half2_rn(v.z, v.w);
    }
    for (int i = tid; i < M_FIX * D_FIX / 4; i += stride) {
        float4 v = ref[i];
        __half2* dst = (__half2*)&g_B[i * 4];
        dst[0] = __floats2half2_rn(v.x, v.y);
        dst[1] = __floats2half2_rn(v.z, v.w);
    }
    for (int i = tid; i < N_FIX; i += stride)
        g_labA[i] = (int)labels[(long long)i * 2];
    for (int i = tid; i < M_FIX; i += stride)
        g_labB[i] = (int)ref_labels[(long long)i * 2];
}

// ---------------------------------------------------------------------------
// PTX helpers
// ---------------------------------------------------------------------------
__device__ __forceinline__ uint32_t smem_u32(const void* p) {
    return (uint32_t)__cvta_generic_to_shared(p);
}
__device__ __forceinline__ void cp16(uint32_t saddr, const void* gaddr) {
    asm volatile("cp.async.cg.shared.global [%0], [%1], 16;" :: "r"(saddr), "l"(gaddr));
}
__device__ __forceinline__ void cp_commit() { asm volatile("cp.async.commit_group;"); }
__device__ __forceinline__ void cp_wait0()  { asm volatile("cp.async.wait_group 0;" ::: "memory"); }

__device__ __forceinline__ void ldsm_x4(uint32_t* r, uint32_t addr) {
    asm volatile("ldmatrix.sync.aligned.m8n8.x4.shared.b16 {%0,%1,%2,%3}, [%4];"
                 : "=r"(r[0]), "=r"(r[1]), "=r"(r[2]), "=r"(r[3]) : "r"(addr));
}

// f16 inputs, f16 accumulators: C fragment = 2 x f16x2 regs
__device__ __forceinline__ void mma_f16(uint32_t* c, const uint32_t* a, uint32_t b0, uint32_t b1) {
    asm volatile(
        "mma.sync.aligned.m16n8k16.row.col.f16.f16.f16.f16 "
        "{%0,%1}, {%2,%3,%4,%5}, {%6,%7}, {%0,%1};"
        : "+r"(c[0]), "+r"(c[1])
        : "r"(a[0]), "r"(a[1]), "r"(a[2]), "r"(a[3]), "r"(b0), "r"(b1));
}

// load a 128x128 fp16 tile (rows of 256B) into padded smem: 2048 x 16B chunks
__device__ __forceinline__ void load_tile(uint32_t sbase, const __half* g, int tid) {
#pragma unroll
    for (int j = 0; j < 4; j++) {
        int idx = tid + j * 512;          // 0..2047
        int r = idx >> 4, c = idx & 15;
        cp16(sbase + r * ROWB + c * 16, g + r * D_FIX + c * 8);
    }
}

// ---------------------------------------------------------------------------
// Persistent fp16 HMMA kernel: 128x128x128 tiles, A resident, B double-buffered
// 512 threads = 16 warps, warp tile 32x32 (4x4 warp grid), f16 accumulators
// ---------------------------------------------------------------------------
__global__ __launch_bounds__(512, 2)
void xbm_h_kernel(float* __restrict__ out) {
    extern __shared__ char smem[];
    const int tid = threadIdx.x, warp = tid >> 5, lane = tid & 31;
    const uint32_t sbase = smem_u32(smem);
    const int* labA_s = (const int*)(smem + SM_LABA);
    float* wsum = (float*)(smem + SM_WSUM);

    int t0 = blockIdx.x * TPC;
    int t1 = t0 + TPC;
    if (t1 > TOT_TILES) t1 = TOT_TILES;
    if (t0 >= t1) { return; }

    const int wm = (warp & 3) * 32;       // row offset of warp tile
    const int wn = (warp >> 2) * 32;      // col offset of warp tile

    // ldmatrix lane-invariant base addresses (k-step advances +32 bytes)
    const uint32_t aBase = sbase + SM_A + (uint32_t)(wm + (lane & 15)) * ROWB
                         + ((lane >> 4) << 4);
    const uint32_t bLane = (uint32_t)(wn + (lane & 7) + ((lane >> 4) << 3)) * ROWB
                         + (((lane >> 3) & 1) << 4);

    // epilogue label indices for this thread
    const int rowA0 = wm + (lane >> 2);
    const int colB0 = wn + ((lane & 3) << 1);

    // prologue: A(nb0) + labA + B(t0) + labB(t0)
    int cur_nb = t0 >> 8;
    {
        int mb = t0 & 255, buf = t0 & 1;
        load_tile(sbase + SM_A, g_A + (size_t)cur_nb * 128 * D_FIX, tid);
        load_tile(sbase + SM_B0 + buf * TILE_SM, g_B + (size_t)mb * 128 * D_FIX, tid);
        if (tid < 32) {
            cp16(sbase + SM_LABA + tid * 16, g_labA + cur_nb * 128 + tid * 4);
            cp16(sbase + SM_LABB0 + buf * 512 + tid * 16, g_labB + mb * 128 + tid * 4);
        }
        cp_commit();
    }

    float ts[4] = {0.0f, 0.0f, 0.0f, 0.0f};   // 4 independent chains

    for (int t = t0; t < t1; ++t) {
        cp_wait0();
        __syncthreads();                      // B(t) (+A) visible to all

        if ((t >> 8) != cur_nb) {             // A is stale for this tile: reload now
            cur_nb = t >> 8;
            load_tile(sbase + SM_A, g_A + (size_t)cur_nb * 128 * D_FIX, tid);
            if (tid < 32) cp16(sbase + SM_LABA + tid * 16, g_labA + cur_nb * 128 + tid * 4);
            cp_commit();
            cp_wait0();
            __syncthreads();
        }

        const int buf = t & 1;
        const uint32_t bBase = sbase + (buf ? SM_B1 : SM_B0) + bLane;
        const int* labB_s = (const int*)(smem + (buf ? SM_LABB1 : SM_LABB0));

        // prefetch next B while computing (overwrites buf^1 = tile t-1's buffer)
        if (t + 1 < t1) {
            int nmb = (t + 1) & 255, nbuf = (t + 1) & 1;
            load_tile(sbase + SM_B0 + nbuf * TILE_SM, g_B + (size_t)nmb * 128 * D_FIX, tid);
            if (tid < 32) cp16(sbase + SM_LABB0 + nbuf * 512 + tid * 16,
                               g_labB + nmb * 128 + tid * 4);
            cp_commit();
        }

        // ---- compute 32x32 warp tile, K=128 (8 k-steps of 16), f16 acc ----
        uint32_t acc[2][4][2];
#pragma unroll
        for (int mi = 0; mi < 2; mi++)
#pragma unroll
            for (int ni = 0; ni < 4; ni++) {
                acc[mi][ni][0] = 0u; acc[mi][ni][1] = 0u;
            }

#pragma unroll
        for (int ks = 0; ks < 8; ks++) {
            const int k0 = ks * 32;            // byte offset
            uint32_t a[2][4], b[2][4];
#pragma unroll
            for (int mi = 0; mi < 2; mi++)
                ldsm_x4(a[mi], aBase + mi * (16 * ROWB) + k0);
#pragma unroll
            for (int p = 0; p < 2; p++)
                ldsm_x4(b[p], bBase + p * (16 * ROWB) + k0);
#pragma unroll
            for (int mi = 0; mi < 2; mi++)
#pragma unroll
                for (int ni = 0; ni < 4; ni++)
                    mma_f16(acc[mi][ni], a[mi],
                            b[ni >> 1][(ni & 1) * 2], b[ni >> 1][(ni & 1) * 2 + 1]);
        }

        // ---- epilogue: unpack f16x2, branchless, 4 independent chains ----
#pragma unroll
        for (int mi = 0; mi < 2; mi++) {
            const int la0 = labA_s[rowA0 + mi * 16];
            const int la1 = labA_s[rowA0 + mi * 16 + 8];
#pragma unroll
            for (int ni = 0; ni < 4; ni++) {
                const int lb0 = labB_s[colB0 + ni * 8];
                const int lb1 = labB_s[colB0 + ni * 8 + 1];
                const float2 lo = __half22float2(*(const __half2*)&acc[mi][ni][0]);
                const float2 hi = __half22float2(*(const __half2*)&acc[mi][ni][1]);
                const float sv[4] = {lo.x, lo.y, hi.x, hi.y};
#pragma unroll
                for (int k = 0; k < 4; k++) {
                    const float s = sv[k];
                    const int lA = (k >> 1) ? la1 : la0;
                    const int lB = (k & 1) ? lb1 : lb0;
                    float v;
                    if (lA == lB) v = fmaxf(1.0f - s, 0.0f);
                    else          v = (s > MARGIN) ? s : 0.0f;
                    ts[k] += v;
                }
            }
        }
    }

    // block reduce + single atomic
    float tsum = (ts[0] + ts[1]) + (ts[2] + ts[3]);
#pragma unroll
    for (int off = 16; off > 0; off >>= 1)
        tsum += __shfl_down_sync(0xFFFFFFFFu, tsum, off);
    if (lane == 0) wsum[warp] = tsum;
    __syncthreads();
    if (tid == 0) {
        float s = 0.0f;
#pragma unroll
        for (int i = 0; i < 16; i++) s += wsum[i];
        atomicAdd(out, s * INV_N);
    }
}

// ---------------------------------------------------------------------------
extern "C" void kernel_launch(void* const* d_in, const int* in_sizes, int n_in,
                              void* d_out, int out_size) {
    const float*     emb        = (const float*)d_in[0];
    const long long* labels     = (const long long*)d_in[1];
    const float*     ref        = (const float*)d_in[2];
    const long long* ref_labels = (const long long*)d_in[3];
    float* out = (float*)d_out;

    cudaFuncSetAttribute(xbm_h_kernel,
                         cudaFuncAttributeMaxDynamicSharedMemorySize, SM_TOTAL);

    prep_kernel<<<512, 256>>>((const float4*)emb, labels, (const float4*)ref,
                              ref_labels, out);
    xbm_h_kernel<<<CTAS, 512, SM_TOTAL>>>(out);
}

// round 17
// speedup vs baseline: 1.0801x; 1.0038x over previous
#include <cuda_runtime.h>
#include <cuda_fp16.h>
#include <cstdint>

// Problem shape: n=4096, m=32768, d=128
#define N_FIX 4096
#define M_FIX 32768
#define D_FIX 128
#define TOT_TILES 8192          // (4096/128) * (32768/128)
#define CTAS 304
#define TPC 27                  // ceil(8192/304)
#define MARGIN 0.5f
#define INV_N (1.0f / 4096.0f)

#define ROWB 272                // padded smem row stride (bytes): 256B data + 16B pad
#define TILE_SM (128 * ROWB)    // 34816 B

// smem layout (bytes)
#define SM_A     0
#define SM_B0    34816
#define SM_B1    69632
#define SM_LABA  104448
#define SM_LABB0 104960
#define SM_LABB1 105472
#define SM_WSUM  105984         // 16 floats
#define SM_TOTAL 106048

// fp16 scratch (allocation-free rule: __device__ globals)
__device__ __half g_A[N_FIX * D_FIX];
__device__ __half g_B[M_FIX * D_FIX];
__device__ int g_labA[N_FIX];
__device__ int g_labB[M_FIX];

// ---------------------------------------------------------------------------
// Prep: fp32 -> fp16, label extraction (level 0), out zeroing
// ---------------------------------------------------------------------------
__global__ void prep_kernel(const float4* __restrict__ emb,
                            const long long* __restrict__ labels,
                            const float4* __restrict__ ref,
                            const long long* __restrict__ ref_labels,
                            float* __restrict__ out) {
    int tid = blockIdx.x * blockDim.x + threadIdx.x;
    int stride = gridDim.x * blockDim.x;
    if (tid == 0) out[0] = 0.0f;
    for (int i = tid; i < N_FIX * D_FIX / 4; i += stride) {
        float4 v = emb[i];
        __half2* dst = (__half2*)&g_A[i * 4];
        dst[0] = __floats2half2_rn(v.x, v.y);
        dst[1] = __floats2half2_rn(v.z, v.w);
    }
    for (int i = tid; i < M_FIX * D_FIX / 4; i += stride) {
        float4 v = ref[i];
        __half2* dst = (__half2*)&g_B[i * 4];
        dst[0] = __floats2half2_rn(v.x, v.y);
        dst[1] = __floats2half2_rn(v.z, v.w);
    }
    for (int i = tid; i < N_FIX; i += stride)
        g_labA[i] = (int)labels[(long long)i * 2];
    for (int i = tid; i < M_FIX; i += stride)
        g_labB[i] = (int)ref_labels[(long long)i * 2];
}

// ---------------------------------------------------------------------------
// PTX helpers
// ---------------------------------------------------------------------------
__device__ __forceinline__ uint32_t smem_u32(const void* p) {
    return (uint32_t)__cvta_generic_to_shared(p);
}
__device__ __forceinline__ void cp16(uint32_t saddr, const void* gaddr) {
    asm volatile("cp.async.cg.shared.global [%0], [%1], 16;" :: "r"(saddr), "l"(gaddr));
}
__device__ __forceinline__ void cp_commit() { asm volatile("cp.async.commit_group;"); }
__device__ __forceinline__ void cp_wait0()  { asm volatile("cp.async.wait_group 0;" ::: "memory"); }

__device__ __forceinline__ void ldsm_x4(uint32_t* r, uint32_t addr) {
    asm volatile("ldmatrix.sync.aligned.m8n8.x4.shared.b16 {%0,%1,%2,%3}, [%4];"
                 : "=r"(r[0]), "=r"(r[1]), "=r"(r[2]), "=r"(r[3]) : "r"(addr));
}

// f16 inputs, f16 accumulators: C fragment = 2 x f16x2 regs
__device__ __forceinline__ void mma_f16(uint32_t* c, const uint32_t* a, uint32_t b0, uint32_t b1) {
    asm volatile(
        "mma.sync.aligned.m16n8k16.row.col.f16.f16.f16.f16 "
        "{%0,%1}, {%2,%3,%4,%5}, {%6,%7}, {%0,%1};"
        : "+r"(c[0]), "+r"(c[1])
        : "r"(a[0]), "r"(a[1]), "r"(a[2]), "r"(a[3]), "r"(b0), "r"(b1));
}

// load a 128x128 fp16 tile (rows of 256B) into padded smem: 2048 x 16B chunks
__device__ __forceinline__ void load_tile(uint32_t sbase, const __half* g, int tid) {
#pragma unroll
    for (int j = 0; j < 4; j++) {
        int idx = tid + j * 512;          // 0..2047
        int r = idx >> 4, c = idx & 15;
        cp16(sbase + r * ROWB + c * 16, g + r * D_FIX + c * 8);
    }
}

// ---------------------------------------------------------------------------
// Persistent fp16 HMMA kernel: 128x128x128 tiles, A resident, B double-buffered
// 512 threads = 16 warps, warp tile 32x32 (4x4 warp grid), f16 accumulators
// ---------------------------------------------------------------------------
__global__ __launch_bounds__(512, 2)
void xbm_h_kernel(float* __restrict__ out) {
    extern __shared__ char smem[];
    const int tid = threadIdx.x, warp = tid >> 5, lane = tid & 31;
    const uint32_t sbase = smem_u32(smem);
    const int* labA_s = (const int*)(smem + SM_LABA);
    float* wsum = (float*)(smem + SM_WSUM);

    int t0 = blockIdx.x * TPC;
    int t1 = t0 + TPC;
    if (t1 > TOT_TILES) t1 = TOT_TILES;
    if (t0 >= t1) { return; }

    const int wm = (warp & 3) * 32;       // row offset of warp tile
    const int wn = (warp >> 2) * 32;      // col offset of warp tile

    // ldmatrix lane-invariant base addresses (k-step advances +32 bytes)
    const uint32_t aBase = sbase + SM_A + (uint32_t)(wm + (lane & 15)) * ROWB
                         + ((lane >> 4) << 4);
    const uint32_t bLane = (uint32_t)(wn + (lane & 7) + ((lane >> 4) << 3)) * ROWB
                         + (((lane >> 3) & 1) << 4);

    // epilogue label indices for this thread
    const int rowA0 = wm + (lane >> 2);
    const int colB0 = wn + ((lane & 3) << 1);

    // prologue: A(nb0) + labA + B(t0) + labB(t0)
    int cur_nb = t0 >> 8;
    {
        int mb = t0 & 255, buf = t0 & 1;
        load_tile(sbase + SM_A, g_A + (size_t)cur_nb * 128 * D_FIX, tid);
        load_tile(sbase + SM_B0 + buf * TILE_SM, g_B + (size_t)mb * 128 * D_FIX, tid);
        if (tid < 32) {
            cp16(sbase + SM_LABA + tid * 16, g_labA + cur_nb * 128 + tid * 4);
            cp16(sbase + SM_LABB0 + buf * 512 + tid * 16, g_labB + mb * 128 + tid * 4);
        }
        cp_commit();
    }

    float ts[4] = {0.0f, 0.0f, 0.0f, 0.0f};   // 4 independent chains

    for (int t = t0; t < t1; ++t) {
        cp_wait0();
        __syncthreads();                      // B(t) (+A) visible to all

        if ((t >> 8) != cur_nb) {             // A is stale for this tile: reload now
            cur_nb = t >> 8;
            load_tile(sbase + SM_A, g_A + (size_t)cur_nb * 128 * D_FIX, tid);
            if (tid < 32) cp16(sbase + SM_LABA + tid * 16, g_labA + cur_nb * 128 + tid * 4);
            cp_commit();
            cp_wait0();
            __syncthreads();
        }

        const int buf = t & 1;
        const uint32_t bBase = sbase + (buf ? SM_B1 : SM_B0) + bLane;
        const int* labB_s = (const int*)(smem + (buf ? SM_LABB1 : SM_LABB0));

        // prefetch next B while computing (overwrites buf^1 = tile t-1's buffer)
        if (t + 1 < t1) {
            int nmb = (t + 1) & 255, nbuf = (t + 1) & 1;
            load_tile(sbase + SM_B0 + nbuf * TILE_SM, g_B + (size_t)nmb * 128 * D_FIX, tid);
            if (tid < 32) cp16(sbase + SM_LABB0 + nbuf * 512 + tid * 16,
                               g_labB + nmb * 128 + tid * 4);
            cp_commit();
        }

        // ---- compute 32x32 warp tile, K=128 (8 k-steps of 16), f16 acc ----
        uint32_t acc[2][4][2];
#pragma unroll
        for (int mi = 0; mi < 2; mi++)
#pragma unroll
            for (int ni = 0; ni < 4; ni++) {
                acc[mi][ni][0] = 0u; acc[mi][ni][1] = 0u;
            }

#pragma unroll
        for (int ks = 0; ks < 8; ks++) {
            const int k0 = ks * 32;            // byte offset
            uint32_t a[2][4], b[2][4];
#pragma unroll
            for (int mi = 0; mi < 2; mi++)
                ldsm_x4(a[mi], aBase + mi * (16 * ROWB) + k0);
#pragma unroll
            for (int p = 0; p < 2; p++)
                ldsm_x4(b[p], bBase + p * (16 * ROWB) + k0);
#pragma unroll
            for (int mi = 0; mi < 2; mi++)
#pragma unroll
                for (int ni = 0; ni < 4; ni++)
                    mma_f16(acc[mi][ni], a[mi],
                            b[ni >> 1][(ni & 1) * 2], b[ni >> 1][(ni & 1) * 2 + 1]);
        }

        // ---- epilogue: unpack f16x2, branchless, 4 independent chains ----
#pragma unroll
        for (int mi = 0; mi < 2; mi++) {
            const int la0 = labA_s[rowA0 + mi * 16];
            const int la1 = labA_s[rowA0 + mi * 16 + 8];
#pragma unroll
            for (int ni = 0; ni < 4; ni++) {
                const int lb0 = labB_s[colB0 + ni * 8];
                const int lb1 = labB_s[colB0 + ni * 8 + 1];
                const float2 lo = __half22float2(*(const __half2*)&acc[mi][ni][0]);
                const float2 hi = __half22float2(*(const __half2*)&acc[mi][ni][1]);
                const float sv[4] = {lo.x, lo.y, hi.x, hi.y};
#pragma unroll
                for (int k = 0; k < 4; k++) {
                    const float s = sv[k];
                    const int lA = (k >> 1) ? la1 : la0;
                    const int lB = (k & 1) ? lb1 : lb0;
                    float v;
                    if (lA == lB) v = fmaxf(1.0f - s, 0.0f);
                    else          v = (s > MARGIN) ? s : 0.0f;
                    ts[k] += v;
                }
            }
        }
    }

    // block reduce + single atomic
    float tsum = (ts[0] + ts[1]) + (ts[2] + ts[3]);
#pragma unroll
    for (int off = 16; off > 0; off >>= 1)
        tsum += __shfl_down_sync(0xFFFFFFFFu, tsum, off);
    if (lane == 0) wsum[warp] = tsum;
    __syncthreads();
    if (tid == 0) {
        float s = 0.0f;
#pragma unroll
        for (int i = 0; i < 16; i++) s += wsum[i];
        atomicAdd(out, s * INV_N);
    }
}

// ---------------------------------------------------------------------------
extern "C" void kernel_launch(void* const* d_in, const int* in_sizes, int n_in,
                              void* d_out, int out_size) {
    const float*     emb        = (const float*)d_in[0];
    const long long* labels     = (const long long*)d_in[1];
    const float*     ref        = (const float*)d_in[2];
    const long long* ref_labels = (const long long*)d_in[3];
    float* out = (float*)d_out;

    cudaFuncSetAttribute(xbm_h_kernel,
                         cudaFuncAttributeMaxDynamicSharedMemorySize, SM_TOTAL);

    prep_kernel<<<512, 256>>>((const float4*)emb, labels, (const float4*)ref,
                              ref_labels, out);
    xbm_h_kernel<<<CTAS, 512, SM_TOTAL>>>(out);
}